// round 3
// baseline (speedup 1.0000x reference)
#include <cuda_runtime.h>
#include <math.h>

#define N_Q   8192
#define M_KV  8192
#define DIM   256
#define KNB   32
#define TAU_F 0.07f
#define EPS_F 1e-8f

#define BM 128
#define BN 128
#define BK 16
#define SSTA 132   // As row stride (floats): 128 + 4 pad
#define SSTB 264   // Bs row stride (floats): 256 (duplicated pairs) + 8 pad

// scratch (device globals: allocation-free per harness rules)
__device__ float g_F[16384 * 256];                 // 16 MB  features pre-norm
__device__ float g_fxn[8192 * 256];                // 8 MB   normalized x-features, row-major
__device__ float g_fynT[256 * 8192];               // 8 MB   normalized y-features, TRANSPOSED [D][M]
__device__ float g_sim[(size_t)8192 * 8192];       // 256 MB similarity matrix

typedef unsigned long long u64;
typedef unsigned int u32;

__device__ __forceinline__ u64 dup2(float f) {
    u64 r; asm("mov.b64 %0, {%1, %1};" : "=l"(r) : "f"(f)); return r;
}
__device__ __forceinline__ void unpk2(u64 p, float& lo, float& hi) {
    asm("mov.b64 {%0, %1}, %2;" : "=f"(lo), "=f"(hi) : "l"(p));
}
// packed fp32x2 FMA: 2 FMA lanes per instruction (PTX-only; ptxas never auto-fuses)
__device__ __forceinline__ void ffma2(u64& d, u64 a, u64 b) {
    asm("fma.rn.f32x2 %0, %1, %2, %0;" : "+l"(d) : "l"(a), "l"(b));
}

// ---------------------------------------------------------------------------
// Shared GEMM body: 128 threads, 128x128 tile, thread tile 16(M, as 8 f32x2
// row-pairs) x 8(N). A read as natural u64 row-pairs (no dup); B duplicated
// at smem-store time. LDS = 128 B per 128 FMA per thread per kk -> crossbar
// (128 B/cyc/SM) and f32x2 FMA pipe (128 FMA/cyc/SM) saturate together.
// ---------------------------------------------------------------------------

// Kernel 1: F = [x;y] @ W^T + b   (M=16384, N=256, K=256)
__global__ __launch_bounds__(128, 2)
void feat_gemm_kernel(const float* __restrict__ x, const float* __restrict__ y,
                      const float* __restrict__ W, const float* __restrict__ bias)
{
    __shared__ __align__(16) float As[BK * SSTA];   // As[k][r] = A[r0+r][k0+k]
    __shared__ __align__(16) float Bs[BK * SSTB];   // Bs[k][2c..2c+1] = B dup
    const int tid = threadIdx.x;
    const int tr  = tid >> 4;          // 0..7  -> rows tr*16 .. +15
    const int tc  = tid & 15;          // 0..15 -> cols tc*8 .. +7
    const int r0  = blockIdx.y * BM;
    const int c0  = blockIdx.x * BN;

    u64 acc[8][8];
#pragma unroll
    for (int i = 0; i < 8; i++)
#pragma unroll
        for (int j = 0; j < 8; j++) acc[i][j] = 0ull;

    for (int k0 = 0; k0 < DIM; k0 += BK) {
        // A tile: [128 rows][16 k] -> As[k][r]
#pragma unroll
        for (int ld = 0; ld < 4; ld++) {
            int pos = tid + ld * 128;          // 0..511
            int r   = pos >> 2;                // 0..127
            int kg  = pos & 3;
            int gr  = r0 + r;
            const float* src = (gr < N_Q) ? (x + (size_t)gr * DIM)
                                          : (y + (size_t)(gr - N_Q) * DIM);
            float4 v = *(const float4*)(src + k0 + kg * 4);
            As[(kg * 4 + 0) * SSTA + r] = v.x;
            As[(kg * 4 + 1) * SSTA + r] = v.y;
            As[(kg * 4 + 2) * SSTA + r] = v.z;
            As[(kg * 4 + 3) * SSTA + r] = v.w;
        }
        // B tile: Bs[k][2c] = dup(W[c0+c][k0+k])
#pragma unroll
        for (int ld = 0; ld < 4; ld++) {
            int pos = tid + ld * 128;
            int c   = pos >> 2;                // 0..127
            int kg  = pos & 3;
            float4 v = *(const float4*)(W + (size_t)(c0 + c) * DIM + k0 + kg * 4);
            *(u64*)(Bs + (kg * 4 + 0) * SSTB + 2 * c) = dup2(v.x);
            *(u64*)(Bs + (kg * 4 + 1) * SSTB + 2 * c) = dup2(v.y);
            *(u64*)(Bs + (kg * 4 + 2) * SSTB + 2 * c) = dup2(v.z);
            *(u64*)(Bs + (kg * 4 + 3) * SSTB + 2 * c) = dup2(v.w);
        }
        __syncthreads();
#pragma unroll
        for (int kk = 0; kk < BK; kk++) {
            const u64* ap = (const u64*)(As + kk * SSTA) + tr * 8;  // 8 row-pairs
            const u64* bp = (const u64*)(Bs + kk * SSTB) + tc * 8;  // 8 dup cols
            u64 a[8], b[8];
#pragma unroll
            for (int i = 0; i < 8; i++) a[i] = ap[i];
#pragma unroll
            for (int j = 0; j < 8; j++) b[j] = bp[j];
#pragma unroll
            for (int i = 0; i < 8; i++)
#pragma unroll
                for (int j = 0; j < 8; j++) ffma2(acc[i][j], a[i], b[j]);
        }
        __syncthreads();
    }

    float bl[8];
#pragma unroll
    for (int u = 0; u < 8; u++) bl[u] = bias[c0 + tc * 8 + u];
#pragma unroll
    for (int p = 0; p < 8; p++) {
        float lo[8], hi[8];
#pragma unroll
        for (int j = 0; j < 8; j++) { unpk2(acc[p][j], lo[j], hi[j]); lo[j] += bl[j]; hi[j] += bl[j]; }
        int row = r0 + tr * 16 + 2 * p;
        float* d0 = g_F + (size_t)row * DIM + c0 + tc * 8;
        float* d1 = d0 + DIM;
        *(float4*)(d0)     = make_float4(lo[0], lo[1], lo[2], lo[3]);
        *(float4*)(d0 + 4) = make_float4(lo[4], lo[5], lo[6], lo[7]);
        *(float4*)(d1)     = make_float4(hi[0], hi[1], hi[2], hi[3]);
        *(float4*)(d1 + 4) = make_float4(hi[4], hi[5], hi[6], hi[7]);
    }
}

// ---------------------------------------------------------------------------
// Kernel 2: L2-normalize rows of F. x-rows -> g_fxn, y-rows -> g_fynT [D][M]
// ---------------------------------------------------------------------------
__global__ __launch_bounds__(256)
void normalize_kernel()
{
    const int row = blockIdx.x;
    const int t   = threadIdx.x;          // 0..255 == feature index
    float v = g_F[(size_t)row * DIM + t];
    float sq = v * v;
#pragma unroll
    for (int o = 16; o > 0; o >>= 1) sq += __shfl_xor_sync(0xffffffffu, sq, o);
    __shared__ float ws[8];
    __shared__ float sres;
    if ((t & 31) == 0) ws[t >> 5] = sq;
    __syncthreads();
    if (t < 32) {
        float total = (t < 8) ? ws[t] : 0.0f;
#pragma unroll
        for (int o = 4; o > 0; o >>= 1) total += __shfl_xor_sync(0xffffffffu, total, o);
        if (t == 0) sres = rsqrtf(total + EPS_F);
    }
    __syncthreads();
    float s = sres;
    float o = v * s;
    if (row < N_Q) g_fxn[(size_t)row * DIM + t] = o;
    else           g_fynT[(size_t)t * M_KV + (row - N_Q)] = o;
}

// ---------------------------------------------------------------------------
// Kernel 3: sim = fxn @ fynT   (8192 x 8192 x 256)
// ---------------------------------------------------------------------------
__global__ __launch_bounds__(128, 2)
void sim_gemm_kernel()
{
    __shared__ __align__(16) float As[BK * SSTA];
    __shared__ __align__(16) float Bs[BK * SSTB];
    const int tid = threadIdx.x;
    const int tr  = tid >> 4;
    const int tc  = tid & 15;
    const int r0  = blockIdx.y * BM;
    const int c0  = blockIdx.x * BN;

    u64 acc[8][8];
#pragma unroll
    for (int i = 0; i < 8; i++)
#pragma unroll
        for (int j = 0; j < 8; j++) acc[i][j] = 0ull;

    for (int k0 = 0; k0 < DIM; k0 += BK) {
        // A tile (g_fxn row-major) -> As[k][r]
#pragma unroll
        for (int ld = 0; ld < 4; ld++) {
            int pos = tid + ld * 128;
            int r   = pos >> 2;
            int kg  = pos & 3;
            float4 v = *(const float4*)(g_fxn + (size_t)(r0 + r) * DIM + k0 + kg * 4);
            As[(kg * 4 + 0) * SSTA + r] = v.x;
            As[(kg * 4 + 1) * SSTA + r] = v.y;
            As[(kg * 4 + 2) * SSTA + r] = v.z;
            As[(kg * 4 + 3) * SSTA + r] = v.w;
        }
        // B tile (g_fynT, k-rows contiguous over columns) -> duplicated pairs
#pragma unroll
        for (int ld = 0; ld < 4; ld++) {
            int pos = tid + ld * 128;
            int k   = pos >> 5;                // 0..15
            int cg  = pos & 31;                // 32 float4 groups cover 128 cols
            float4 v = *(const float4*)(g_fynT + (size_t)(k0 + k) * M_KV + c0 + cg * 4);
            u64* dst = (u64*)(Bs + k * SSTB) + cg * 4;
            dst[0] = dup2(v.x); dst[1] = dup2(v.y);
            dst[2] = dup2(v.z); dst[3] = dup2(v.w);
        }
        __syncthreads();
#pragma unroll
        for (int kk = 0; kk < BK; kk++) {
            const u64* ap = (const u64*)(As + kk * SSTA) + tr * 8;
            const u64* bp = (const u64*)(Bs + kk * SSTB) + tc * 8;
            u64 a[8], b[8];
#pragma unroll
            for (int i = 0; i < 8; i++) a[i] = ap[i];
#pragma unroll
            for (int j = 0; j < 8; j++) b[j] = bp[j];
#pragma unroll
            for (int i = 0; i < 8; i++)
#pragma unroll
                for (int j = 0; j < 8; j++) ffma2(acc[i][j], a[i], b[j]);
        }
        __syncthreads();
    }
#pragma unroll
    for (int p = 0; p < 8; p++) {
        float lo[8], hi[8];
#pragma unroll
        for (int j = 0; j < 8; j++) unpk2(acc[p][j], lo[j], hi[j]);
        int row = r0 + tr * 16 + 2 * p;
        float* d0 = g_sim + (size_t)row * M_KV + c0 + tc * 8;
        float* d1 = d0 + M_KV;
        *(float4*)(d0)     = make_float4(lo[0], lo[1], lo[2], lo[3]);
        *(float4*)(d0 + 4) = make_float4(lo[4], lo[5], lo[6], lo[7]);
        *(float4*)(d1)     = make_float4(hi[0], hi[1], hi[2], hi[3]);
        *(float4*)(d1 + 4) = make_float4(hi[4], hi[5], hi[6], hi[7]);
    }
}

// ---------------------------------------------------------------------------
// Kernel 4: exact top-32 per row via packed-key warpsort.
// key = (ord(val) << 32) | ~idx  — unsigned compare == (val desc, idx asc),
// matching jax.lax.top_k tie-breaking exactly.
// ---------------------------------------------------------------------------
__device__ __forceinline__ u32 ordf(float f) {
    u32 b = __float_as_uint(f);
    return (b & 0x80000000u) ? ~b : (b | 0x80000000u);
}
__device__ __forceinline__ float key_val(u64 k) {
    u32 o = (u32)(k >> 32);
    u32 b = (o & 0x80000000u) ? (o ^ 0x80000000u) : ~o;
    return __uint_as_float(b);
}
__device__ __forceinline__ u64 make_key(float v, int idx) {
    return ((u64)ordf(v) << 32) | (u32)(~(u32)idx);
}
__device__ __forceinline__ u64 kmax(u64 a, u64 b) { return a > b ? a : b; }
__device__ __forceinline__ u64 kmin(u64 a, u64 b) { return a < b ? a : b; }
__device__ __forceinline__ u64 shflx(u64 v, int m) {
    return __shfl_xor_sync(0xffffffffu, v, m);
}

// Sort c descending across the warp, then merge top-32 of (L ∪ c) into L.
__device__ __forceinline__ void merge32(u64& L, u64 c, int lane)
{
#pragma unroll
    for (int k = 2; k <= 32; k <<= 1) {
#pragma unroll
        for (int j = k >> 1; j > 0; j >>= 1) {
            u64 o = shflx(c, j);
            bool lower = (lane & j) == 0;
            bool desc  = (lane & k) == 0;
            c = (lower == desc) ? kmax(c, o) : kmin(c, o);
        }
    }
    u64 cr = shflx(c, 31);          // reverse -> ascending
    L = kmax(L, cr);                // pairwise max -> bitonic
#pragma unroll
    for (int j = 16; j > 0; j >>= 1) {
        u64 o = shflx(L, j);
        bool lower = (lane & j) == 0;
        L = lower ? kmax(L, o) : kmin(L, o);
    }
}

__global__ __launch_bounds__(256)
void topk_kernel(float* __restrict__ out, int out_size)
{
    __shared__ u64 sbuf[8][64];
    const unsigned FULL = 0xffffffffu;
    const int warp = threadIdx.x >> 5;
    const int lane = threadIdx.x & 31;
    const int row  = blockIdx.x * 8 + warp;
    u64* buf = sbuf[warp];
    const float* rp = g_sim + (size_t)row * M_KV;

    u64   list = (u64)ordf(-3.0e38f) << 32;   // 32 sentinels
    float mn   = -3.0e38f;
    int   cnt  = 0;

    for (int base = 0; base < M_KV; base += 256) {
        float4 u = *(const float4*)(rp + base + lane * 4);
        float4 w = *(const float4*)(rp + base + 128 + lane * 4);
        float c[8] = {u.x, u.y, u.z, u.w, w.x, w.y, w.z, w.w};
        float m8 = fmaxf(fmaxf(fmaxf(c[0], c[1]), fmaxf(c[2], c[3])),
                         fmaxf(fmaxf(c[4], c[5]), fmaxf(c[6], c[7])));
        if (!__ballot_sync(FULL, m8 > mn)) continue;   // common fast path
#pragma unroll
        for (int q = 0; q < 8; q++) {
            unsigned bal = __ballot_sync(FULL, c[q] > mn);
            if (bal) {
                bool mine = (c[q] > mn);
                int pos = cnt + __popc(bal & ((1u << lane) - 1));
                int col = base + (q >> 2) * 128 + lane * 4 + (q & 3);
                if (mine) buf[pos] = make_key(c[q], col);
                cnt += __popc(bal);
                while (cnt >= 32) {
                    __syncwarp();
                    u64 cd = buf[lane];
                    if (lane < cnt - 32) buf[lane] = buf[32 + lane];
                    __syncwarp();
                    cnt -= 32;
                    merge32(list, cd, lane);
                    mn = key_val(__shfl_sync(FULL, list, 31));
                }
            }
        }
    }
    if (cnt > 0) {
        __syncwarp();
        u64 cd = (lane < cnt) ? buf[lane] : 0ull;   // key 0 < every real key
        merge32(list, cd, lane);
    }

    // decode + temperature softmax over the 32 (list sorted desc by key)
    float v   = key_val(list);
    int   idx = (int)(~(u32)list);
    float top = __shfl_sync(FULL, v, 0);
    float e = expf((v - top) / TAU_F);
    float s = e;
#pragma unroll
    for (int o = 16; o > 0; o >>= 1) s += __shfl_xor_sync(FULL, s, o);
    float soft = e / s;

    out[(size_t)row * KNB + lane] = soft;
    if (out_size >= 2 * N_Q * KNB)
        out[(size_t)N_Q * KNB + (size_t)row * KNB + lane] = (float)idx;
}

// ---------------------------------------------------------------------------
extern "C" void kernel_launch(void* const* d_in, const int* in_sizes, int n_in,
                              void* d_out, int out_size)
{
    const float* x = (const float*)d_in[0];
    const float* y = (const float*)d_in[1];
    const float* W = (const float*)d_in[2];
    const float* b = (const float*)d_in[3];
    float* out = (float*)d_out;
    (void)in_sizes; (void)n_in;

    feat_gemm_kernel<<<dim3(DIM / BN, (N_Q + M_KV) / BM), 128>>>(x, y, W, b);
    normalize_kernel<<<N_Q + M_KV, 256>>>();
    sim_gemm_kernel<<<dim3(M_KV / BN, N_Q / BM), 128>>>();
    topk_kernel<<<N_Q / 8, 256>>>(out, out_size);
}

// round 9
// speedup vs baseline: 1.4203x; 1.4203x over previous
#include <cuda_runtime.h>
#include <cuda_bf16.h>
#include <math.h>
#include <stdint.h>

#define N_Q   8192
#define M_KV  8192
#define DIM   256
#define KNB   32
#define TAU_F 0.07f
#define EPS_F 1e-8f

#define KCAT  768    // 3 split-term segments x 256  (hh + hm + mh)

// ---------------- scratch (device globals; allocation-free) ----------------
__device__ float g_F[16384 * 256];                          // 16 MB features pre-norm
__device__ float g_fxn[(size_t)N_Q * DIM];                  // 8 MB fp32 normalized x
__device__ float g_fyn[(size_t)M_KV * DIM];                 // 8 MB fp32 normalized y
__device__ __nv_bfloat16 g_axc[(size_t)N_Q * KCAT];         // 12 MB A concat splits (h,h,m)
__device__ __nv_bfloat16 g_byc[(size_t)M_KV * KCAT];        // 12 MB B concat splits (h,m,h)
__device__ float g_sim[(size_t)N_Q * M_KV];                 // 256 MB approx similarity

typedef unsigned long long u64;
typedef unsigned int u32;

// ---------------- f32x2 helpers (feat GEMM) ----------------
__device__ __forceinline__ u64 pk2(float lo, float hi) {
    u64 r; asm("mov.b64 %0, {%1, %2};" : "=l"(r) : "f"(lo), "f"(hi)); return r;
}
__device__ __forceinline__ void unpk2(u64 p, float& lo, float& hi) {
    asm("mov.b64 {%0, %1}, %2;" : "=f"(lo), "=f"(hi) : "l"(p));
}
__device__ __forceinline__ void ffma2(u64& d, u64 a, u64 b) {
    asm("fma.rn.f32x2 %0, %1, %2, %0;" : "+l"(d) : "l"(a), "l"(b));
}

// ---------------------------------------------------------------------------
// Kernel 1: F = [x;y] @ W^T + b   (fp32 exact; R1 body — best measured)
// ---------------------------------------------------------------------------
#define FBM 128
#define FBN 128
#define FBK 16
#define FSST 132

__global__ __launch_bounds__(256, 2)
void feat_gemm_kernel(const float* __restrict__ x, const float* __restrict__ y,
                      const float* __restrict__ W, const float* __restrict__ bias)
{
    __shared__ float As[FBK * FSST];
    __shared__ float Bs[FBK * FSST];
    const int tid = threadIdx.x;
    const int tr  = tid >> 4;
    const int tc  = tid & 15;
    const int r0  = blockIdx.y * FBM;
    const int c0  = blockIdx.x * FBN;

    u64 acc[8][4];
#pragma unroll
    for (int i = 0; i < 8; i++)
#pragma unroll
        for (int j = 0; j < 4; j++) acc[i][j] = 0ull;

    for (int k0 = 0; k0 < DIM; k0 += FBK) {
#pragma unroll
        for (int ld = 0; ld < 2; ld++) {
            int pos = tid + ld * 256;
            int r   = pos >> 2;
            int kg  = pos & 3;
            int gr  = r0 + r;
            const float* src = (gr < N_Q) ? (x + (size_t)gr * DIM)
                                          : (y + (size_t)(gr - N_Q) * DIM);
            float4 v = *(const float4*)(src + k0 + kg * 4);
            As[(kg * 4 + 0) * FSST + r] = v.x;
            As[(kg * 4 + 1) * FSST + r] = v.y;
            As[(kg * 4 + 2) * FSST + r] = v.z;
            As[(kg * 4 + 3) * FSST + r] = v.w;
        }
#pragma unroll
        for (int ld = 0; ld < 2; ld++) {
            int pos = tid + ld * 256;
            int c   = pos >> 2;
            int kg  = pos & 3;
            float4 v = *(const float4*)(W + (size_t)(c0 + c) * DIM + k0 + kg * 4);
            Bs[(kg * 4 + 0) * FSST + c] = v.x;
            Bs[(kg * 4 + 1) * FSST + c] = v.y;
            Bs[(kg * 4 + 2) * FSST + c] = v.z;
            Bs[(kg * 4 + 3) * FSST + c] = v.w;
        }
        __syncthreads();
#pragma unroll
        for (int kk = 0; kk < FBK; kk++) {
            const float* ar = As + kk * FSST + tr * 8;
            const u64*   br = (const u64*)(Bs + kk * FSST + tc * 8);
            float4 a0 = *(const float4*)(ar);
            float4 a1 = *(const float4*)(ar + 4);
            u64 b0 = br[0], b1 = br[1], b2 = br[2], b3 = br[3];
            float av[8] = {a0.x, a0.y, a0.z, a0.w, a1.x, a1.y, a1.z, a1.w};
#pragma unroll
            for (int i = 0; i < 8; i++) {
                u64 ai = pk2(av[i], av[i]);
                ffma2(acc[i][0], ai, b0);
                ffma2(acc[i][1], ai, b1);
                ffma2(acc[i][2], ai, b2);
                ffma2(acc[i][3], ai, b3);
            }
        }
        __syncthreads();
    }

    float bl[8];
#pragma unroll
    for (int u = 0; u < 8; u++) bl[u] = bias[c0 + tc * 8 + u];
#pragma unroll
    for (int i = 0; i < 8; i++) {
        int row = r0 + tr * 8 + i;
        float* dst = g_F + (size_t)row * DIM + c0 + tc * 8;
        float4 w0, w1;
        unpk2(acc[i][0], w0.x, w0.y); unpk2(acc[i][1], w0.z, w0.w);
        unpk2(acc[i][2], w1.x, w1.y); unpk2(acc[i][3], w1.z, w1.w);
        w0.x += bl[0]; w0.y += bl[1]; w0.z += bl[2]; w0.w += bl[3];
        w1.x += bl[4]; w1.y += bl[5]; w1.z += bl[6]; w1.w += bl[7];
        *(float4*)dst       = w0;
        *(float4*)(dst + 4) = w1;
    }
}

// ---------------------------------------------------------------------------
// Kernel 2: L2-normalize rows of F; store fp32 (for sequential re-rank) and
// the bf16 split concat operands:  A segs (h,h,m)  B segs (h,m,h)
// sim_approx = h·h' + h·m' + m·h'   (|error| <= ~6e-6, containment margin 1e-2)
// ---------------------------------------------------------------------------
__global__ __launch_bounds__(256)
void normalize_split_kernel()
{
    const int row = blockIdx.x;
    const int t   = threadIdx.x;
    float v = g_F[(size_t)row * DIM + t];
    float sq = v * v;
#pragma unroll
    for (int o = 16; o > 0; o >>= 1) sq += __shfl_xor_sync(0xffffffffu, sq, o);
    __shared__ float ws[8];
    __shared__ float sres;
    if ((t & 31) == 0) ws[t >> 5] = sq;
    __syncthreads();
    if (t < 32) {
        float total = (t < 8) ? ws[t] : 0.0f;
#pragma unroll
        for (int o = 4; o > 0; o >>= 1) total += __shfl_xor_sync(0xffffffffu, total, o);
        if (t == 0) sres = rsqrtf(total + EPS_F);
    }
    __syncthreads();
    float vn = v * sres;

    __nv_bfloat16 h = __float2bfloat16_rn(vn);
    float r1 = vn - __bfloat162float(h);
    __nv_bfloat16 m = __float2bfloat16_rn(r1);

    if (row < N_Q) {
        g_fxn[(size_t)row * DIM + t] = vn;
        __nv_bfloat16* p = g_axc + (size_t)row * KCAT + t;
        p[0*DIM] = h; p[1*DIM] = h; p[2*DIM] = m;
    } else {
        int r = row - N_Q;
        g_fyn[(size_t)r * DIM + t] = vn;
        __nv_bfloat16* p = g_byc + (size_t)r * KCAT + t;
        p[0*DIM] = h; p[1*DIM] = m; p[2*DIM] = h;
    }
}

// ---------------------------------------------------------------------------
// Kernel 3: sim = A_cat @ B_cat^T  (8192 x 8192 x 768) on HMMA (mma.sync,
// bf16 -> fp32). 256x128 CTA tile, 8 warps of 64x64, 12 k-stages of 64,
// 3-stage cp.async pipeline, SW128-swizzled smem + ldmatrix.
// ---------------------------------------------------------------------------
#define SBM 256
#define SBN 128
#define NSTAGE 3
#define A_STG (SBM * 128)
#define B_STG (SBN * 128)
#define STG   (A_STG + B_STG)
#define SIM_SMEM (NSTAGE * STG)       // 144 KB
#define NKSTAGES (KCAT / 64)          // 12

#define SWZ(o) ((o) ^ (((o) >> 3) & 0x70))

__device__ __forceinline__ u32 s2u(const void* p) {
    u32 a; asm("{ .reg .u64 t; cvta.to.shared.u64 t, %1; cvt.u32.u64 %0, t; }"
               : "=r"(a) : "l"(p)); return a;
}
__device__ __forceinline__ void cp16(u32 dst, const void* src) {
    asm volatile("cp.async.cg.shared.global [%0], [%1], 16;"
                 :: "r"(dst), "l"(src) : "memory");
}
__device__ __forceinline__ void ldsm4(u32* r, u32 addr) {
    asm volatile("ldmatrix.sync.aligned.m8n8.x4.shared.b16 {%0,%1,%2,%3}, [%4];"
                 : "=r"(r[0]), "=r"(r[1]), "=r"(r[2]), "=r"(r[3]) : "r"(addr));
}
__device__ __forceinline__ void mma16816(float* c, const u32* a, const u32* b) {
    asm volatile(
        "mma.sync.aligned.m16n8k16.row.col.f32.bf16.bf16.f32 "
        "{%0,%1,%2,%3}, {%4,%5,%6,%7}, {%8,%9}, {%0,%1,%2,%3};"
        : "+f"(c[0]), "+f"(c[1]), "+f"(c[2]), "+f"(c[3])
        : "r"(a[0]), "r"(a[1]), "r"(a[2]), "r"(a[3]), "r"(b[0]), "r"(b[1]));
}

__global__ __launch_bounds__(256, 1)
void sim_mma_kernel()
{
    extern __shared__ char dyn[];
    const u32 sbase = s2u(dyn);
    const int tid  = threadIdx.x;
    const int wid  = tid >> 5;
    const int lane = tid & 31;
    const int wm   = wid >> 1;
    const int wn   = wid & 1;
    const int r0   = blockIdx.y * SBM;
    const int c0   = blockIdx.x * SBN;

    float acc[4][8][4];
#pragma unroll
    for (int i = 0; i < 4; i++)
#pragma unroll
        for (int j = 0; j < 8; j++)
#pragma unroll
            for (int q = 0; q < 4; q++) acc[i][j][q] = 0.0f;

    auto loadStage = [&](int s) {
        const int buf = s % NSTAGE;
        const u32 sA = sbase + buf * STG;
        const u32 sB = sA + A_STG;
        const __nv_bfloat16* gA = g_axc + (size_t)r0 * KCAT + s * 64;
        const __nv_bfloat16* gB = g_byc + (size_t)c0 * KCAT + s * 64;
#pragma unroll
        for (int i = 0; i < 8; i++) {
            int id = tid + i * 256;
            int r = id >> 3, kc = id & 7;
            cp16(sA + SWZ(r * 128 + kc * 16), gA + (size_t)r * KCAT + kc * 8);
        }
#pragma unroll
        for (int i = 0; i < 4; i++) {
            int id = tid + i * 256;
            int r = id >> 3, kc = id & 7;
            cp16(sB + SWZ(r * 128 + kc * 16), gB + (size_t)r * KCAT + kc * 8);
        }
        asm volatile("cp.async.commit_group;" ::: "memory");
    };

    loadStage(0);
    loadStage(1);

    for (int s = 0; s < NKSTAGES; s++) {
        if (s + 2 < NKSTAGES)
            asm volatile("cp.async.wait_group 1;" ::: "memory");
        else
            asm volatile("cp.async.wait_group 0;" ::: "memory");
        __syncthreads();
        if (s + 2 < NKSTAGES) loadStage(s + 2);

        const int buf = s % NSTAGE;
        const u32 sA = sbase + buf * STG;
        const u32 sB = sA + A_STG;

#pragma unroll
        for (int ks = 0; ks < 4; ks++) {
            u32 afr[4][4], bfr[4][4];
#pragma unroll
            for (int mt = 0; mt < 4; mt++) {
                int mr = wm * 64 + mt * 16 + (lane & 15);
                int kb = ks * 32 + (lane >> 4) * 16;
                ldsm4(afr[mt], sA + SWZ(mr * 128 + kb));
            }
#pragma unroll
            for (int np = 0; np < 4; np++) {
                int nr = wn * 64 + np * 16 + ((lane >> 4) & 1) * 8 + (lane & 7);
                int kb = ks * 32 + ((lane >> 3) & 1) * 16;
                ldsm4(bfr[np], sB + SWZ(nr * 128 + kb));
            }
#pragma unroll
            for (int mt = 0; mt < 4; mt++)
#pragma unroll
                for (int nt = 0; nt < 8; nt++)
                    mma16816(acc[mt][nt], afr[mt], &bfr[nt >> 1][(nt & 1) * 2]);
        }
    }

#pragma unroll
    for (int mt = 0; mt < 4; mt++) {
        int rlo = r0 + wm * 64 + mt * 16 + (lane >> 2);
#pragma unroll
        for (int nt = 0; nt < 8; nt++) {
            int col = c0 + wn * 64 + nt * 8 + (lane & 3) * 2;
            float2 v0 = make_float2(acc[mt][nt][0], acc[mt][nt][1]);
            float2 v1 = make_float2(acc[mt][nt][2], acc[mt][nt][3]);
            *(float2*)(g_sim + (size_t)rlo * M_KV + col)       = v0;
            *(float2*)(g_sim + (size_t)(rlo + 8) * M_KV + col) = v1;
        }
    }
}

// ---------------------------------------------------------------------------
// Kernel 4: stream approx top-64 per row (packed-key warpsort, 2-reg list),
// then recompute the 64 candidate dots with a SEQUENTIAL fp32 FMA chain over
// k ascending — bit-matching the R1 SIMT kernel's arithmetic, which
// empirically matched the reference's ordering (zero idx flips). Exact
// top-32 select (val desc, idx asc), temperature softmax.
// ---------------------------------------------------------------------------
__device__ __forceinline__ u32 ordf(float f) {
    u32 b = __float_as_uint(f);
    return (b & 0x80000000u) ? ~b : (b | 0x80000000u);
}
__device__ __forceinline__ float key_val(u64 k) {
    u32 o = (u32)(k >> 32);
    u32 b = (o & 0x80000000u) ? (o ^ 0x80000000u) : ~o;
    return __uint_as_float(b);
}
__device__ __forceinline__ u64 make_key(float v, int idx) {
    return ((u64)ordf(v) << 32) | (u32)(~(u32)idx);
}
__device__ __forceinline__ u64 kmax(u64 a, u64 b) { return a > b ? a : b; }
__device__ __forceinline__ u64 kmin(u64 a, u64 b) { return a < b ? a : b; }
__device__ __forceinline__ u64 shflx(u64 v, int m) {
    return __shfl_xor_sync(0xffffffffu, v, m);
}
// full bitonic sort desc across warp
__device__ __forceinline__ void sort32(u64& c, int lane) {
#pragma unroll
    for (int k = 2; k <= 32; k <<= 1) {
#pragma unroll
        for (int j = k >> 1; j > 0; j >>= 1) {
            u64 o = shflx(c, j);
            bool lower = (lane & j) == 0;
            bool desc  = (lane & k) == 0;
            c = (lower == desc) ? kmax(c, o) : kmin(c, o);
        }
    }
}
// bitonic sequence -> sorted desc (5-stage clean-up)
__device__ __forceinline__ void bimerge32(u64& L, int lane) {
#pragma unroll
    for (int j = 16; j > 0; j >>= 1) {
        u64 o = shflx(L, j);
        bool lower = (lane & j) == 0;
        L = lower ? kmax(L, o) : kmin(L, o);
    }
}
// merge sorted-desc 64-list with 32 new candidates; keep top-64 sorted desc.
__device__ __forceinline__ void merge64(u64& L0, u64& L1, u64 c, int lane) {
    sort32(c, lane);                 // desc
    u64 cr = shflx(c, 31);           // asc
    L1 = kmax(L1, cr);               // top-32 of L1∪c (bitonic)
    bimerge32(L1, lane);             // -> sorted desc
    u64 l1r = shflx(L1, 31);         // asc; (L0 desc | l1r asc) = bitonic-64
    u64 hi = kmax(L0, l1r);
    u64 lo = kmin(L0, l1r);
    bimerge32(hi, lane);
    bimerge32(lo, lane);
    L0 = hi; L1 = lo;
}

__global__ __launch_bounds__(256)
void topk_kernel(float* __restrict__ out, int out_size)
{
    __shared__ u64 sbuf[8][64];
    __shared__ int scid[8][64];
    __shared__ float ssfx[8][256];
    const unsigned FULL = 0xffffffffu;
    const int warp = threadIdx.x >> 5;
    const int lane = threadIdx.x & 31;
    const int row  = blockIdx.x * 8 + warp;
    u64* buf = sbuf[warp];
    int* cid = scid[warp];
    float* sfx = ssfx[warp];
    const float* rp = g_sim + (size_t)row * M_KV;

    const u64 SENT = (u64)ordf(-3.0e38f) << 32;
    u64 L0 = SENT, L1 = SENT;
    float mn = -3.0e38f;
    int cnt = 0;

    for (int base = 0; base < M_KV; base += 256) {
        float4 u = *(const float4*)(rp + base + lane * 4);
        float4 w = *(const float4*)(rp + base + 128 + lane * 4);
        float c[8] = {u.x, u.y, u.z, u.w, w.x, w.y, w.z, w.w};
        float m8 = fmaxf(fmaxf(fmaxf(c[0], c[1]), fmaxf(c[2], c[3])),
                         fmaxf(fmaxf(c[4], c[5]), fmaxf(c[6], c[7])));
        if (!__ballot_sync(FULL, m8 > mn)) continue;
#pragma unroll
        for (int q = 0; q < 8; q++) {
            unsigned bal = __ballot_sync(FULL, c[q] > mn);
            if (bal) {
                bool mine = (c[q] > mn);
                int pos = cnt + __popc(bal & ((1u << lane) - 1));
                int col = base + (q >> 2) * 128 + lane * 4 + (q & 3);
                if (mine) buf[pos] = make_key(c[q], col);
                cnt += __popc(bal);
                while (cnt >= 32) {
                    __syncwarp();
                    u64 cd = buf[lane];
                    if (lane < cnt - 32) buf[lane] = buf[32 + lane];
                    __syncwarp();
                    cnt -= 32;
                    merge64(L0, L1, cd, lane);
                    mn = key_val(__shfl_sync(FULL, L1, 31));
                }
            }
        }
    }
    if (cnt > 0) {
        __syncwarp();
        u64 cd = (lane < cnt) ? buf[lane] : 0ull;
        merge64(L0, L1, cd, lane);
    }

    // ---- sequential-fp32 re-rank of the 64 candidates (R1 arithmetic) ----
    int c0i = (int)(~(u32)L0);
    int c1i = (int)(~(u32)L1);
    // stage fx row in shared (8 floats per lane)
    {
        float4 a = *(const float4*)(g_fxn + (size_t)row * DIM + lane * 8);
        float4 b = *(const float4*)(g_fxn + (size_t)row * DIM + lane * 8 + 4);
        *(float4*)(sfx + lane * 8)     = a;
        *(float4*)(sfx + lane * 8 + 4) = b;
    }
    __syncwarp();

    const float* fy0 = g_fyn + (size_t)c0i * DIM;
    const float* fy1 = g_fyn + (size_t)c1i * DIM;
    float p0 = 0.0f, p1 = 0.0f;
#pragma unroll 4
    for (int k = 0; k < DIM; k += 4) {
        float4 b0 = *(const float4*)(fy0 + k);
        float4 b1 = *(const float4*)(fy1 + k);
        float a0 = sfx[k], a1 = sfx[k+1], a2 = sfx[k+2], a3 = sfx[k+3];
        p0 = fmaf(a0, b0.x, p0); p1 = fmaf(a0, b1.x, p1);
        p0 = fmaf(a1, b0.y, p0); p1 = fmaf(a1, b1.y, p1);
        p0 = fmaf(a2, b0.z, p0); p1 = fmaf(a2, b1.z, p1);
        p0 = fmaf(a3, b0.w, p0); p1 = fmaf(a3, b1.w, p1);
    }
    u64 ex0 = make_key(p0, c0i);
    u64 ex1 = make_key(p1, c1i);

    // exact top-32 of the 64: sort both halves desc, bitonic top-merge
    sort32(ex0, lane);
    sort32(ex1, lane);
    u64 r1 = shflx(ex1, 31);
    ex0 = kmax(ex0, r1);
    bimerge32(ex0, lane);

    float v   = key_val(ex0);
    int   idx = (int)(~(u32)ex0);
    float top = __shfl_sync(FULL, v, 0);
    float e = expf((v - top) / TAU_F);
    float s = e;
#pragma unroll
    for (int o = 16; o > 0; o >>= 1) s += __shfl_xor_sync(FULL, s, o);
    float soft = e / s;

    out[(size_t)row * KNB + lane] = soft;
    if (out_size >= 2 * N_Q * KNB)
        out[(size_t)N_Q * KNB + (size_t)row * KNB + lane] = (float)idx;
}

// ---------------------------------------------------------------------------
extern "C" void kernel_launch(void* const* d_in, const int* in_sizes, int n_in,
                              void* d_out, int out_size)
{
    const float* x = (const float*)d_in[0];
    const float* y = (const float*)d_in[1];
    const float* W = (const float*)d_in[2];
    const float* b = (const float*)d_in[3];
    float* out = (float*)d_out;
    (void)in_sizes; (void)n_in;

    cudaFuncSetAttribute(sim_mma_kernel,
                         cudaFuncAttributeMaxDynamicSharedMemorySize, SIM_SMEM);

    feat_gemm_kernel<<<dim3(DIM / FBN, (N_Q + M_KV) / FBM), 256>>>(x, y, W, b);
    normalize_split_kernel<<<N_Q + M_KV, 256>>>();
    sim_mma_kernel<<<dim3(M_KV / SBN, N_Q / SBM), 256, SIM_SMEM>>>();
    topk_kernel<<<N_Q / 8, 256>>>(out, out_size);
}

// round 10
// speedup vs baseline: 2.1035x; 1.4811x over previous
#include <cuda_runtime.h>
#include <cuda_bf16.h>
#include <math.h>
#include <stdint.h>

#define N_Q   8192
#define M_KV  8192
#define DIM   256
#define KNB   32
#define TAU_F 0.07f
#define EPS_F 1e-8f

#define KCAT  768    // 3 split-term segments x 256  (hh + hm + mh)

// ---------------- scratch (device globals; allocation-free) ----------------
__device__ float g_F[16384 * 256];                          // 16 MB features pre-norm
__device__ float g_fxn[(size_t)N_Q * DIM];                  // 8 MB fp32 normalized x
__device__ float g_fyn[(size_t)M_KV * DIM];                 // 8 MB fp32 normalized y
__device__ __nv_bfloat16 g_axc[(size_t)N_Q * KCAT];         // 12 MB A concat splits (h,h,m)
__device__ __nv_bfloat16 g_byc[(size_t)M_KV * KCAT];        // 12 MB B concat splits (h,m,h)
__device__ float g_sim[(size_t)N_Q * M_KV];                 // 256 MB approx similarity

typedef unsigned long long u64;
typedef unsigned int u32;

// ---------------- f32x2 helpers (feat GEMM) ----------------
__device__ __forceinline__ u64 pk2(float lo, float hi) {
    u64 r; asm("mov.b64 %0, {%1, %2};" : "=l"(r) : "f"(lo), "f"(hi)); return r;
}
__device__ __forceinline__ void unpk2(u64 p, float& lo, float& hi) {
    asm("mov.b64 {%0, %1}, %2;" : "=f"(lo), "=f"(hi) : "l"(p));
}
__device__ __forceinline__ void ffma2(u64& d, u64 a, u64 b) {
    asm("fma.rn.f32x2 %0, %1, %2, %0;" : "+l"(d) : "l"(a), "l"(b));
}

// ---------------------------------------------------------------------------
// Kernel 1: F = [x;y] @ W^T + b   (fp32 exact; R1 body — best measured)
// ---------------------------------------------------------------------------
#define FBM 128
#define FBN 128
#define FBK 16
#define FSST 132

__global__ __launch_bounds__(256, 2)
void feat_gemm_kernel(const float* __restrict__ x, const float* __restrict__ y,
                      const float* __restrict__ W, const float* __restrict__ bias)
{
    __shared__ float As[FBK * FSST];
    __shared__ float Bs[FBK * FSST];
    const int tid = threadIdx.x;
    const int tr  = tid >> 4;
    const int tc  = tid & 15;
    const int r0  = blockIdx.y * FBM;
    const int c0  = blockIdx.x * FBN;

    u64 acc[8][4];
#pragma unroll
    for (int i = 0; i < 8; i++)
#pragma unroll
        for (int j = 0; j < 4; j++) acc[i][j] = 0ull;

    for (int k0 = 0; k0 < DIM; k0 += FBK) {
#pragma unroll
        for (int ld = 0; ld < 2; ld++) {
            int pos = tid + ld * 256;
            int r   = pos >> 2;
            int kg  = pos & 3;
            int gr  = r0 + r;
            const float* src = (gr < N_Q) ? (x + (size_t)gr * DIM)
                                          : (y + (size_t)(gr - N_Q) * DIM);
            float4 v = *(const float4*)(src + k0 + kg * 4);
            As[(kg * 4 + 0) * FSST + r] = v.x;
            As[(kg * 4 + 1) * FSST + r] = v.y;
            As[(kg * 4 + 2) * FSST + r] = v.z;
            As[(kg * 4 + 3) * FSST + r] = v.w;
        }
#pragma unroll
        for (int ld = 0; ld < 2; ld++) {
            int pos = tid + ld * 256;
            int c   = pos >> 2;
            int kg  = pos & 3;
            float4 v = *(const float4*)(W + (size_t)(c0 + c) * DIM + k0 + kg * 4);
            Bs[(kg * 4 + 0) * FSST + c] = v.x;
            Bs[(kg * 4 + 1) * FSST + c] = v.y;
            Bs[(kg * 4 + 2) * FSST + c] = v.z;
            Bs[(kg * 4 + 3) * FSST + c] = v.w;
        }
        __syncthreads();
#pragma unroll
        for (int kk = 0; kk < FBK; kk++) {
            const float* ar = As + kk * FSST + tr * 8;
            const u64*   br = (const u64*)(Bs + kk * FSST + tc * 8);
            float4 a0 = *(const float4*)(ar);
            float4 a1 = *(const float4*)(ar + 4);
            u64 b0 = br[0], b1 = br[1], b2 = br[2], b3 = br[3];
            float av[8] = {a0.x, a0.y, a0.z, a0.w, a1.x, a1.y, a1.z, a1.w};
#pragma unroll
            for (int i = 0; i < 8; i++) {
                u64 ai = pk2(av[i], av[i]);
                ffma2(acc[i][0], ai, b0);
                ffma2(acc[i][1], ai, b1);
                ffma2(acc[i][2], ai, b2);
                ffma2(acc[i][3], ai, b3);
            }
        }
        __syncthreads();
    }

    float bl[8];
#pragma unroll
    for (int u = 0; u < 8; u++) bl[u] = bias[c0 + tc * 8 + u];
#pragma unroll
    for (int i = 0; i < 8; i++) {
        int row = r0 + tr * 8 + i;
        float* dst = g_F + (size_t)row * DIM + c0 + tc * 8;
        float4 w0, w1;
        unpk2(acc[i][0], w0.x, w0.y); unpk2(acc[i][1], w0.z, w0.w);
        unpk2(acc[i][2], w1.x, w1.y); unpk2(acc[i][3], w1.z, w1.w);
        w0.x += bl[0]; w0.y += bl[1]; w0.z += bl[2]; w0.w += bl[3];
        w1.x += bl[4]; w1.y += bl[5]; w1.z += bl[6]; w1.w += bl[7];
        *(float4*)dst       = w0;
        *(float4*)(dst + 4) = w1;
    }
}

// ---------------------------------------------------------------------------
// Kernel 2: L2-normalize rows of F; store fp32 (for sequential re-rank) and
// the bf16 split concat operands:  A segs (h,h,m)  B segs (h,m,h)
// ---------------------------------------------------------------------------
__global__ __launch_bounds__(256)
void normalize_split_kernel()
{
    const int row = blockIdx.x;
    const int t   = threadIdx.x;
    float v = g_F[(size_t)row * DIM + t];
    float sq = v * v;
#pragma unroll
    for (int o = 16; o > 0; o >>= 1) sq += __shfl_xor_sync(0xffffffffu, sq, o);
    __shared__ float ws[8];
    __shared__ float sres;
    if ((t & 31) == 0) ws[t >> 5] = sq;
    __syncthreads();
    if (t < 32) {
        float total = (t < 8) ? ws[t] : 0.0f;
#pragma unroll
        for (int o = 4; o > 0; o >>= 1) total += __shfl_xor_sync(0xffffffffu, total, o);
        if (t == 0) sres = rsqrtf(total + EPS_F);
    }
    __syncthreads();
    float vn = v * sres;

    __nv_bfloat16 h = __float2bfloat16_rn(vn);
    float r1 = vn - __bfloat162float(h);
    __nv_bfloat16 m = __float2bfloat16_rn(r1);

    if (row < N_Q) {
        g_fxn[(size_t)row * DIM + t] = vn;
        __nv_bfloat16* p = g_axc + (size_t)row * KCAT + t;
        p[0*DIM] = h; p[1*DIM] = h; p[2*DIM] = m;
    } else {
        int r = row - N_Q;
        g_fyn[(size_t)r * DIM + t] = vn;
        __nv_bfloat16* p = g_byc + (size_t)r * KCAT + t;
        p[0*DIM] = h; p[1*DIM] = m; p[2*DIM] = h;
    }
}

// ---------------------------------------------------------------------------
// Kernel 3: sim = A_cat @ B_cat^T  (8192 x 8192 x 768) on HMMA (mma.sync,
// bf16 -> fp32). 256x128 CTA tile, 8 warps of 64x64, 12 k-stages of 64,
// 3-stage cp.async pipeline, SW128-swizzled smem + ldmatrix.  (unchanged)
// ---------------------------------------------------------------------------
#define SBM 256
#define SBN 128
#define NSTAGE 3
#define A_STG (SBM * 128)
#define B_STG (SBN * 128)
#define STG   (A_STG + B_STG)
#define SIM_SMEM (NSTAGE * STG)       // 144 KB
#define NKSTAGES (KCAT / 64)          // 12

#define SWZ(o) ((o) ^ (((o) >> 3) & 0x70))

__device__ __forceinline__ u32 s2u(const void* p) {
    u32 a; asm("{ .reg .u64 t; cvta.to.shared.u64 t, %1; cvt.u32.u64 %0, t; }"
               : "=r"(a) : "l"(p)); return a;
}
__device__ __forceinline__ void cp16(u32 dst, const void* src) {
    asm volatile("cp.async.cg.shared.global [%0], [%1], 16;"
                 :: "r"(dst), "l"(src) : "memory");
}
__device__ __forceinline__ void ldsm4(u32* r, u32 addr) {
    asm volatile("ldmatrix.sync.aligned.m8n8.x4.shared.b16 {%0,%1,%2,%3}, [%4];"
                 : "=r"(r[0]), "=r"(r[1]), "=r"(r[2]), "=r"(r[3]) : "r"(addr));
}
__device__ __forceinline__ void mma16816(float* c, const u32* a, const u32* b) {
    asm volatile(
        "mma.sync.aligned.m16n8k16.row.col.f32.bf16.bf16.f32 "
        "{%0,%1,%2,%3}, {%4,%5,%6,%7}, {%8,%9}, {%0,%1,%2,%3};"
        : "+f"(c[0]), "+f"(c[1]), "+f"(c[2]), "+f"(c[3])
        : "r"(a[0]), "r"(a[1]), "r"(a[2]), "r"(a[3]), "r"(b[0]), "r"(b[1]));
}

__global__ __launch_bounds__(256, 1)
void sim_mma_kernel()
{
    extern __shared__ char dyn[];
    const u32 sbase = s2u(dyn);
    const int tid  = threadIdx.x;
    const int wid  = tid >> 5;
    const int lane = tid & 31;
    const int wm   = wid >> 1;
    const int wn   = wid & 1;
    const int r0   = blockIdx.y * SBM;
    const int c0   = blockIdx.x * SBN;

    float acc[4][8][4];
#pragma unroll
    for (int i = 0; i < 4; i++)
#pragma unroll
        for (int j = 0; j < 8; j++)
#pragma unroll
            for (int q = 0; q < 4; q++) acc[i][j][q] = 0.0f;

    auto loadStage = [&](int s) {
        const int buf = s % NSTAGE;
        const u32 sA = sbase + buf * STG;
        const u32 sB = sA + A_STG;
        const __nv_bfloat16* gA = g_axc + (size_t)r0 * KCAT + s * 64;
        const __nv_bfloat16* gB = g_byc + (size_t)c0 * KCAT + s * 64;
#pragma unroll
        for (int i = 0; i < 8; i++) {
            int id = tid + i * 256;
            int r = id >> 3, kc = id & 7;
            cp16(sA + SWZ(r * 128 + kc * 16), gA + (size_t)r * KCAT + kc * 8);
        }
#pragma unroll
        for (int i = 0; i < 4; i++) {
            int id = tid + i * 256;
            int r = id >> 3, kc = id & 7;
            cp16(sB + SWZ(r * 128 + kc * 16), gB + (size_t)r * KCAT + kc * 8);
        }
        asm volatile("cp.async.commit_group;" ::: "memory");
    };

    loadStage(0);
    loadStage(1);

    for (int s = 0; s < NKSTAGES; s++) {
        if (s + 2 < NKSTAGES)
            asm volatile("cp.async.wait_group 1;" ::: "memory");
        else
            asm volatile("cp.async.wait_group 0;" ::: "memory");
        __syncthreads();
        if (s + 2 < NKSTAGES) loadStage(s + 2);

        const int buf = s % NSTAGE;
        const u32 sA = sbase + buf * STG;
        const u32 sB = sA + A_STG;

#pragma unroll
        for (int ks = 0; ks < 4; ks++) {
            u32 afr[4][4], bfr[4][4];
#pragma unroll
            for (int mt = 0; mt < 4; mt++) {
                int mr = wm * 64 + mt * 16 + (lane & 15);
                int kb = ks * 32 + (lane >> 4) * 16;
                ldsm4(afr[mt], sA + SWZ(mr * 128 + kb));
            }
#pragma unroll
            for (int np = 0; np < 4; np++) {
                int nr = wn * 64 + np * 16 + ((lane >> 4) & 1) * 8 + (lane & 7);
                int kb = ks * 32 + ((lane >> 3) & 1) * 16;
                ldsm4(bfr[np], sB + SWZ(nr * 128 + kb));
            }
#pragma unroll
            for (int mt = 0; mt < 4; mt++)
#pragma unroll
                for (int nt = 0; nt < 8; nt++)
                    mma16816(acc[mt][nt], afr[mt], &bfr[nt >> 1][(nt & 1) * 2]);
        }
    }

#pragma unroll
    for (int mt = 0; mt < 4; mt++) {
        int rlo = r0 + wm * 64 + mt * 16 + (lane >> 2);
#pragma unroll
        for (int nt = 0; nt < 8; nt++) {
            int col = c0 + wn * 64 + nt * 8 + (lane & 3) * 2;
            float2 v0 = make_float2(acc[mt][nt][0], acc[mt][nt][1]);
            float2 v1 = make_float2(acc[mt][nt][2], acc[mt][nt][3]);
            *(float2*)(g_sim + (size_t)rlo * M_KV + col)       = v0;
            *(float2*)(g_sim + (size_t)(rlo + 8) * M_KV + col) = v1;
        }
    }
}

// ---------------------------------------------------------------------------
// Kernel 4: stream approx top-64 per row, then sequential-fp32 re-rank via
// SMEM-STAGED candidate tiles (coalesced loads; identical summation order to
// the R9-passing version), exact top-32 select, temperature softmax.
// 128 threads / 4 warps per block (one row per warp).
// ---------------------------------------------------------------------------
__device__ __forceinline__ u32 ordf(float f) {
    u32 b = __float_as_uint(f);
    return (b & 0x80000000u) ? ~b : (b | 0x80000000u);
}
__device__ __forceinline__ float key_val(u64 k) {
    u32 o = (u32)(k >> 32);
    u32 b = (o & 0x80000000u) ? (o ^ 0x80000000u) : ~o;
    return __uint_as_float(b);
}
__device__ __forceinline__ u64 make_key(float v, int idx) {
    return ((u64)ordf(v) << 32) | (u32)(~(u32)idx);
}
__device__ __forceinline__ u64 kmax(u64 a, u64 b) { return a > b ? a : b; }
__device__ __forceinline__ u64 kmin(u64 a, u64 b) { return a < b ? a : b; }
__device__ __forceinline__ u64 shflx(u64 v, int m) {
    return __shfl_xor_sync(0xffffffffu, v, m);
}
// full bitonic sort desc across warp
__device__ __forceinline__ void sort32(u64& c, int lane) {
#pragma unroll
    for (int k = 2; k <= 32; k <<= 1) {
#pragma unroll
        for (int j = k >> 1; j > 0; j >>= 1) {
            u64 o = shflx(c, j);
            bool lower = (lane & j) == 0;
            bool desc  = (lane & k) == 0;
            c = (lower == desc) ? kmax(c, o) : kmin(c, o);
        }
    }
}
// bitonic sequence -> sorted desc (5-stage clean-up)
__device__ __forceinline__ void bimerge32(u64& L, int lane) {
#pragma unroll
    for (int j = 16; j > 0; j >>= 1) {
        u64 o = shflx(L, j);
        bool lower = (lane & j) == 0;
        L = lower ? kmax(L, o) : kmin(L, o);
    }
}
// merge sorted-desc 64-list with 32 new candidates; keep top-64 sorted desc.
__device__ __forceinline__ void merge64(u64& L0, u64& L1, u64 c, int lane) {
    sort32(c, lane);                 // desc
    u64 cr = shflx(c, 31);           // asc
    L1 = kmax(L1, cr);               // top-32 of L1∪c (bitonic)
    bimerge32(L1, lane);             // -> sorted desc
    u64 l1r = shflx(L1, 31);         // asc; (L0 desc | l1r asc) = bitonic-64
    u64 hi = kmax(L0, l1r);
    u64 lo = kmin(L0, l1r);
    bimerge32(hi, lane);
    bimerge32(lo, lane);
    L0 = hi; L1 = lo;
}

#define TK_WARPS 4

__global__ __launch_bounds__(128)
void topk_kernel(float* __restrict__ out, int out_size)
{
    __shared__ u64   sbuf[TK_WARPS][64];
    __shared__ int   scid[TK_WARPS][64];
    __shared__ float ssfx[TK_WARPS][256];
    __shared__ float stile[TK_WARPS][32][65];   // [kk][cand], pad 65 keeps banks clean
    const unsigned FULL = 0xffffffffu;
    const int warp = threadIdx.x >> 5;
    const int lane = threadIdx.x & 31;
    const int row  = blockIdx.x * TK_WARPS + warp;
    u64* buf = sbuf[warp];
    int* cid = scid[warp];
    float* sfx = ssfx[warp];
    const float* rp = g_sim + (size_t)row * M_KV;

    const u64 SENT = (u64)ordf(-3.0e38f) << 32;
    u64 L0 = SENT, L1 = SENT;
    float mn = -3.0e38f;
    int cnt = 0;

    for (int base = 0; base < M_KV; base += 256) {
        float4 u = *(const float4*)(rp + base + lane * 4);
        float4 w = *(const float4*)(rp + base + 128 + lane * 4);
        float c[8] = {u.x, u.y, u.z, u.w, w.x, w.y, w.z, w.w};
        float m8 = fmaxf(fmaxf(fmaxf(c[0], c[1]), fmaxf(c[2], c[3])),
                         fmaxf(fmaxf(c[4], c[5]), fmaxf(c[6], c[7])));
        if (!__ballot_sync(FULL, m8 > mn)) continue;
#pragma unroll
        for (int q = 0; q < 8; q++) {
            unsigned bal = __ballot_sync(FULL, c[q] > mn);
            if (bal) {
                bool mine = (c[q] > mn);
                int pos = cnt + __popc(bal & ((1u << lane) - 1));
                int col = base + (q >> 2) * 128 + lane * 4 + (q & 3);
                if (mine) buf[pos] = make_key(c[q], col);
                cnt += __popc(bal);
                while (cnt >= 32) {
                    __syncwarp();
                    u64 cd = buf[lane];
                    if (lane < cnt - 32) buf[lane] = buf[32 + lane];
                    __syncwarp();
                    cnt -= 32;
                    merge64(L0, L1, cd, lane);
                    mn = key_val(__shfl_sync(FULL, L1, 31));
                }
            }
        }
    }
    if (cnt > 0) {
        __syncwarp();
        u64 cd = (lane < cnt) ? buf[lane] : 0ull;
        merge64(L0, L1, cd, lane);
    }

    // ---- sequential-fp32 re-rank (R9 arithmetic) with smem staging ----
    int c0i = (int)(~(u32)L0);        // candidate rank lane
    int c1i = (int)(~(u32)L1);        // candidate rank lane+32
    cid[lane]      = c0i;
    cid[lane + 32] = c1i;
    {
        float4 a = *(const float4*)(g_fxn + (size_t)row * DIM + lane * 8);
        float4 b = *(const float4*)(g_fxn + (size_t)row * DIM + lane * 8 + 4);
        *(float4*)(sfx + lane * 8)     = a;
        *(float4*)(sfx + lane * 8 + 4) = b;
    }
    __syncwarp();

    float p0 = 0.0f, p1 = 0.0f;
    for (int c8 = 0; c8 < 8; c8++) {
        const int k0 = c8 * 32;
        // stage 64 candidate rows x 32 k-values, coalesced (4 lines/LDG)
#pragma unroll
        for (int it = 0; it < 16; it++) {
            int r  = it * 4 + (lane >> 3);       // 0..63
            int f4 = lane & 7;                   // 8 float4 per row-chunk
            float4 v = *(const float4*)(g_fyn + (size_t)cid[r] * DIM + k0 + f4 * 4);
            stile[warp][f4 * 4 + 0][r] = v.x;
            stile[warp][f4 * 4 + 1][r] = v.y;
            stile[warp][f4 * 4 + 2][r] = v.z;
            stile[warp][f4 * 4 + 3][r] = v.w;
        }
        __syncwarp();
        // sequential fp32 FMA chain over k ascending (bit-identical to R9)
#pragma unroll
        for (int kk = 0; kk < 32; kk++) {
            float a = sfx[k0 + kk];
            p0 = fmaf(a, stile[warp][kk][lane],      p0);
            p1 = fmaf(a, stile[warp][kk][lane + 32], p1);
        }
        __syncwarp();
    }
    u64 ex0 = make_key(p0, c0i);
    u64 ex1 = make_key(p1, c1i);

    // exact top-32 of the 64: sort both halves desc, bitonic top-merge
    sort32(ex0, lane);
    sort32(ex1, lane);
    u64 r1 = shflx(ex1, 31);
    ex0 = kmax(ex0, r1);
    bimerge32(ex0, lane);

    float v   = key_val(ex0);
    int   idx = (int)(~(u32)ex0);
    float top = __shfl_sync(FULL, v, 0);
    float e = expf((v - top) / TAU_F);
    float s = e;
#pragma unroll
    for (int o = 16; o > 0; o >>= 1) s += __shfl_xor_sync(FULL, s, o);
    float soft = e / s;

    out[(size_t)row * KNB + lane] = soft;
    if (out_size >= 2 * N_Q * KNB)
        out[(size_t)N_Q * KNB + (size_t)row * KNB + lane] = (float)idx;
}

// ---------------------------------------------------------------------------
extern "C" void kernel_launch(void* const* d_in, const int* in_sizes, int n_in,
                              void* d_out, int out_size)
{
    const float* x = (const float*)d_in[0];
    const float* y = (const float*)d_in[1];
    const float* W = (const float*)d_in[2];
    const float* b = (const float*)d_in[3];
    float* out = (float*)d_out;
    (void)in_sizes; (void)n_in;

    cudaFuncSetAttribute(sim_mma_kernel,
                         cudaFuncAttributeMaxDynamicSharedMemorySize, SIM_SMEM);

    feat_gemm_kernel<<<dim3(DIM / FBN, (N_Q + M_KV) / FBM), 256>>>(x, y, W, b);
    normalize_split_kernel<<<N_Q + M_KV, 256>>>();
    sim_mma_kernel<<<dim3(M_KV / SBN, N_Q / SBM), 256, SIM_SMEM>>>();
    topk_kernel<<<N_Q / TK_WARPS, 128>>>(out, out_size);
}